// round 13
// baseline (speedup 1.0000x reference)
#include <cuda_runtime.h>
#include <cstdint>

/*
 Top-K mask of zero-diagonal outer(p,p), N=8192, K=262144.
 TWO kernels:
  k_select: 32 blocks x 1024 thr (co-residency guaranteed: 32 << 148 SMs,
            1 block/SM at 128KB smem). Software grid barrier. Phases:
            block-0 shared counting sort (validated R9 code) -> all blocks
            copy sorted p to shared -> ~31-iteration EXACT bisection over
            uint32 sortable-key space (1 row per thread per iteration,
            8192 shared-mem binary searches/iter, 1 barrier/iter) ->
            exact K-th key + count(Tk+1) -> tie spans -> block-0 cut.
  k_out:    fused 268MB float4 streaming-store pass (store-roofline bound).
*/

#define N      8192
#define KTOP   262144u
#define NBINS  16384
#define KSHIFT 18
#define TIECAP 4096
#define NB     32
#define TPB    1024
#define MAXIT  48

__device__ float    g_sval[N];
__device__ int      g_sidx[N];
__device__ unsigned g_c[MAXIT];
__device__ unsigned g_tie[TIECAP];
__device__ unsigned g_ntie;
__device__ float    g_thr;
__device__ unsigned g_cut;
__device__ unsigned g_barcnt;
__device__ volatile unsigned g_gen;

__device__ __forceinline__ unsigned fkey(float f) {
    unsigned u = __float_as_uint(f);
    return u ^ (((unsigned)((int)u >> 31)) | 0x80000000u);
}
__device__ __forceinline__ float unflip(unsigned k) {
    unsigned u = (k & 0x80000000u) ? (k ^ 0x80000000u) : ~k;
    return __uint_as_float(u);
}

/* software grid barrier: all NB blocks resident (32 blocks, 1/SM) */
__device__ __forceinline__ void gbar() {
    __threadfence();
    __syncthreads();
    if (threadIdx.x == 0) {
        unsigned old = g_gen;
        if (atomicAdd(&g_barcnt, 1u) == NB - 1u) {
            g_barcnt = 0u;
            __threadfence();
            g_gen = old + 1u;
        } else {
            while (g_gen == old) __nanosleep(128);
        }
    }
    __syncthreads();
}

/* boundary search on SHARED sorted array, range [0,N):
   v>0: pred(m)=(v*s[m]>=T) true for m<b ; count=b
   v<0: pred true for m>=b ; count=N-b */
__device__ __forceinline__ int bsb(float v, float T, const float* s) {
    int lo = 0, hi = N;
    if (v > 0.0f) {
        while (lo < hi) { int m = (lo + hi) >> 1; if (v * s[m] >= T) lo = m + 1; else hi = m; }
    } else {
        while (lo < hi) { int m = (lo + hi) >> 1; if (v * s[m] >= T) hi = m; else lo = m + 1; }
    }
    return lo;
}

__global__ void __launch_bounds__(TPB, 1) k_select(const float* __restrict__ p) {
    extern __shared__ unsigned char sm[];
    unsigned* s_off = (unsigned*)sm;                 /* [16384] 64KB (sort, block 0) */
    float*    s_vs  = (float*)(sm + 65536);          /* [8192] 32KB (sort) */
    int*      s_is  = (int*)(sm + 98304);            /* [8192] 32KB (sort) */
    float*    s_val = (float*)sm;                    /* [8192] 32KB (count; overlaps s_off) */
    __shared__ unsigned cur[TPB];
    __shared__ unsigned s_tie[TIECAP];
    __shared__ unsigned s_cut_sh;

    const int tid = threadIdx.x;
    const int bid = blockIdx.x;
    const int gt  = bid * TPB + tid;

    /* per-launch zeroing of cross-block scratch (before first barrier) */
    if (gt < MAXIT) g_c[gt] = 0u;
    if (gt == MAXIT) g_ntie = 0u;

    /* ================= block 0: validated shared counting sort ============= */
    if (bid == 0) {
        for (int i = tid; i < NBINS; i += TPB) s_off[i] = 0u;
        __syncthreads();

        float pv[8];
        #pragma unroll
        for (int j = 0; j < 8; j++) {
            pv[j] = p[tid + j * 1024];
            atomicAdd(&s_off[fkey(pv[j]) >> KSHIFT], 1u);
        }
        __syncthreads();

        /* suffix scan: s_off[b] = #keys in bins strictly above b */
        {
            const int base = tid * 16;
            unsigned h[16]; unsigned ct = 0;
            #pragma unroll
            for (int j = 0; j < 16; j++) { h[j] = s_off[base + j]; ct += h[j]; }
            cur[tid] = ct; __syncthreads();
            for (int d = 1; d < TPB; d <<= 1) {
                unsigned v2 = cur[tid] + ((tid + d < TPB) ? cur[tid + d] : 0u);
                __syncthreads(); cur[tid] = v2; __syncthreads();
            }
            unsigned g = cur[tid] - ct;
            for (int j = 15; j >= 0; j--) {
                s_off[base + j] = g;
                g += h[j];
            }
        }
        __syncthreads();

        /* scatter (descending by bin) */
        #pragma unroll
        for (int j = 0; j < 8; j++) {
            unsigned b = fkey(pv[j]) >> KSHIFT;
            unsigned pos = atomicAdd(&s_off[b], 1u);
            s_vs[pos] = pv[j];
            s_is[pos] = tid + j * 1024;
        }
        __syncthreads();

        /* per-run insertion fix (exact descending order) */
        for (int i = tid; i < N; i += TPB) {
            unsigned bi = fkey(s_vs[i]) >> KSHIFT;
            if (i > 0 && (fkey(s_vs[i - 1]) >> KSHIFT) == bi) continue;
            int e = i + 1;
            while (e < N && (fkey(s_vs[e]) >> KSHIFT) == bi) e++;
            for (int a = i + 1; a < e; a++) {
                float kv = s_vs[a]; int ki = s_is[a];
                int j = a - 1;
                while (j >= i && s_vs[j] < kv) {
                    s_vs[j + 1] = s_vs[j]; s_is[j + 1] = s_is[j]; j--;
                }
                s_vs[j + 1] = kv; s_is[j + 1] = ki;
            }
        }
        __syncthreads();

        /* publish */
        #pragma unroll
        for (int j = 0; j < 8; j++) {
            int i = tid + j * 1024;
            g_sval[i] = s_vs[i];
            g_sidx[i] = s_is[i];
        }
    }
    gbar();

    /* ================= all blocks: shared copy of sorted values ============ */
    for (int i = tid; i < N; i += TPB) s_val[i] = __ldcg(&g_sval[i]);
    __syncthreads();

    /* ================= exact bisection over key space ====================== */
    unsigned klo = 0x80000000u, khi = 0xFFFFFFFFu, chi = 0u;
    const int row = bid * 256 + tid;              /* valid when tid < 256 */
    const float v = (tid < 256) ? s_val[row] : 0.0f;

    for (int it = 0; it < MAXIT; ++it) {
        if (khi - klo <= 1u) break;               /* uniform across all blocks */
        unsigned mid = klo + ((khi - klo) >> 1);
        float T = unflip(mid);
        unsigned c = 0;
        if (tid < 256 && v != 0.0f) {
            int b = bsb(v, T, s_val);
            c = (v > 0.0f) ? (unsigned)b : (unsigned)(N - b);
            if (v * v >= T) c -= 1u;              /* drop diagonal */
        }
        if (tid < 256) {
            #pragma unroll
            for (int d = 16; d > 0; d >>= 1) c += __shfl_down_sync(0xffffffffu, c, d);
            if ((tid & 31) == 0 && c) atomicAdd(&g_c[it], c);
        }
        gbar();
        unsigned ct = __ldcg(&g_c[it]);
        if (ct >= KTOP) klo = mid; else { khi = mid; chi = ct; }
    }
    const unsigned Tk = klo;
    const float thr  = unflip(Tk);
    const float thr1 = unflip(Tk + 1u);
    const unsigned r = KTOP - chi;                /* chi = count(Tk+1), exact */

    /* ================= tie spans (product key == Tk) ======================= */
    if (tid < 256 && v != 0.0f) {
        int bA = bsb(v, thr,  s_val);
        int bB = bsb(v, thr1, s_val);
        int m0, m1;
        if (v > 0.0f) { m0 = bB; m1 = bA; } else { m0 = bA; m1 = bB; }
        if (m1 > m0) {
            unsigned fb = ((unsigned)__ldcg(&g_sidx[row])) << 13;
            for (int m = m0; m < m1; m++) {
                if (m == row) continue;
                unsigned pos = atomicAdd(&g_ntie, 1u);
                if (pos < TIECAP) g_tie[pos] = fb + (unsigned)__ldcg(&g_sidx[m]);
            }
        }
    }
    gbar();

    /* ================= block 0: smallest-flat-index tie cut ================ */
    if (bid != 0) return;
    {
        unsigned nt = min(__ldcg(&g_ntie), (unsigned)TIECAP);
        for (unsigned i = tid; i < nt; i += TPB) s_tie[i] = __ldcg(&g_tie[i]);
        if (tid == 0) s_cut_sh = (r >= nt) ? 0xFFFFFFFFu : 0u;
        __syncthreads();
        if (r < nt) {
            for (unsigned i = tid; i < nt; i += TPB) {
                unsigned x = s_tie[i];
                unsigned rk = 0;
                for (unsigned j = 0; j < nt; j++) rk += (s_tie[j] < x) ? 1u : 0u;
                if (rk == r) s_cut_sh = x;
            }
        }
        __syncthreads();
        if (tid == 0) { g_thr = thr; g_cut = s_cut_sh; }
    }
}

/* ================= fused output pass (validated, roofline) ================ */
__device__ __forceinline__ float edgev(float v, float thr, unsigned flat, unsigned cut, bool diag) {
    bool ok = ((v > thr) | ((v == thr) & (flat < cut))) & (!diag);
    return ok ? 1.0f : 0.0f;
}

__global__ void k_out(const float* __restrict__ p, float4* __restrict__ out) {
    int row = blockIdx.y;
    float pi = __ldg(p + row);
    float thr = g_thr;
    unsigned cut = g_cut;
    const float4* __restrict__ q4 = (const float4*)p;
    int f0 = blockIdx.x * 1024 + threadIdx.x;
    unsigned fbase = ((unsigned)row) << 13;
    unsigned outrow = ((unsigned)row) << 11;
    #pragma unroll
    for (int k = 0; k < 4; k++) {
        int f = f0 + k * 256;
        float4 q = __ldg(q4 + f);
        unsigned j0 = ((unsigned)f) << 2;
        float4 o;
        o.x = edgev(pi * q.x, thr, fbase + j0 + 0u, cut, (j0 + 0u) == (unsigned)row);
        o.y = edgev(pi * q.y, thr, fbase + j0 + 1u, cut, (j0 + 1u) == (unsigned)row);
        o.z = edgev(pi * q.z, thr, fbase + j0 + 2u, cut, (j0 + 2u) == (unsigned)row);
        o.w = edgev(pi * q.w, thr, fbase + j0 + 3u, cut, (j0 + 3u) == (unsigned)row);
        __stcs(out + outrow + (unsigned)f, o);
    }
}

extern "C" void kernel_launch(void* const* d_in, const int* in_sizes, int n_in,
                              void* d_out, int out_size) {
    const float* p = (const float*)d_in[0];
    float* out = (float*)d_out;
    (void)in_sizes; (void)n_in; (void)out_size;

    const int SMEM = 65536 + 32768 + 32768;   /* 131072 B dynamic */
    cudaFuncSetAttribute(k_select, cudaFuncAttributeMaxDynamicSharedMemorySize, SMEM);

    k_select<<<NB, TPB, SMEM>>>(p);

    dim3 grid(2, N);
    k_out<<<grid, 256>>>(p, (float4*)out);
}

// round 14
// speedup vs baseline: 1.8262x; 1.8262x over previous
#include <cuda_runtime.h>
#include <cstdint>

/*
 Top-K mask of zero-diagonal outer(p,p), N=8192, K=262144.
 Distributed pipeline, NO big-smem mega-block (that was a ~200us pathology):
  k_zero    : zero g_hist/g_cnt1/g_cnt2/g_m
  k_hist    : global 16384-bin hist of hi-14 sortable keys
  k_scan    : 1 small block, suffix scan -> g_off (write cursors)
  k_scatter : scatter p into g_sval/g_sidx (descending by bin)
  k_fix     : per-run insertion fix (exact descending order)
  k_count x2: exact count(>=edge) at 256 edges, 1024 blocks (4 chunks/edge),
              14-step guarded lockstep binary searches, atomic accumulate
  k_enum    : emit (key,flat) for products inside final bracket (re-derives bracket)
  k_exact   : exact K-th key + tie budget + smallest-flat-index cut
  k_out     : fused 268MB float4 streaming-store pass (store-roofline bound)
*/

#define N      8192
#define KTOP   262144u
#define NBINS  16384
#define KSHIFT 18
#define TIECAP 4096
#define CAP    (1u<<20)

__device__ unsigned g_hist[NBINS];
__device__ unsigned g_off[NBINS];
__device__ float    g_sval[N];
__device__ int      g_sidx[N];
__device__ unsigned g_cnt1[256];
__device__ unsigned g_cnt2[256];
__device__ unsigned g_keys[CAP];
__device__ unsigned g_flats[CAP];
__device__ unsigned g_m;
__device__ float    g_thr;
__device__ unsigned g_cut;

__device__ __forceinline__ unsigned fkey(float f) {
    unsigned u = __float_as_uint(f);
    return u ^ (((unsigned)((int)u >> 31)) | 0x80000000u);
}
__device__ __forceinline__ float unflip(unsigned k) {
    unsigned u = (k & 0x80000000u) ? (k ^ 0x80000000u) : ~k;
    return __uint_as_float(u);
}

/* boundary search on g_sval (L1-resident), range [0,N):
   v>0: pred(m)=(v*s[m]>=T) true for m<b ; count=b
   v<0: pred true for m>=b ; count=N-b */
__device__ __forceinline__ int bsb(float v, float T) {
    int lo = 0, hi = N;
    if (v > 0.0f) {
        while (lo < hi) { int m = (lo + hi) >> 1; if (v * __ldg(&g_sval[m]) >= T) lo = m + 1; else hi = m; }
    } else {
        while (lo < hi) { int m = (lo + hi) >> 1; if (v * __ldg(&g_sval[m]) >= T) hi = m; else lo = m + 1; }
    }
    return lo;
}

/* level-1 bracket from g_cnt1 (parallel, first 256 threads participate) */
__device__ __forceinline__ void derive1(unsigned* sh, int tid,
                                        unsigned& lo1, unsigned& hi1,
                                        unsigned& chi1, unsigned& stride2) {
    if (tid == 0) *sh = 0u;
    __syncthreads();
    if (tid < 256 && __ldg(&g_cnt1[tid]) >= KTOP) atomicMax(sh, (unsigned)tid);
    __syncthreads();
    unsigned t1 = *sh;
    lo1 = 0x80000000u + t1 * 0x800000u;
    if (t1 < 255u) { hi1 = lo1 + 0x800000u; chi1 = __ldg(&g_cnt1[t1 + 1u]); }
    else           { hi1 = 0xFFFFFFFFu; chi1 = 0u; }
    stride2 = (hi1 - lo1) >> 8; if (!stride2) stride2 = 1u;
    __syncthreads();
}
/* level-2 bracket from g_cnt2 */
__device__ __forceinline__ void derive2(unsigned* sh, int tid,
                                        unsigned lo1, unsigned hi1, unsigned chi1,
                                        unsigned stride2,
                                        unsigned& lo2, unsigned& hi2, unsigned& chi2) {
    if (tid == 0) *sh = 0u;
    __syncthreads();
    if (tid < 256 && __ldg(&g_cnt2[tid]) >= KTOP) atomicMax(sh, (unsigned)tid);
    __syncthreads();
    unsigned t2 = *sh;
    lo2 = lo1 + t2 * stride2;
    if (t2 < 255u) { hi2 = lo1 + (t2 + 1u) * stride2; chi2 = __ldg(&g_cnt2[t2 + 1u]); }
    else           { hi2 = hi1; chi2 = chi1; }
    __syncthreads();
}

/* ======================= sort pipeline (distributed) ====================== */
__global__ void k_zero() {
    int t = blockIdx.x * blockDim.x + threadIdx.x;
    int st = gridDim.x * blockDim.x;
    for (int i = t; i < NBINS; i += st) g_hist[i] = 0u;
    if (t < 256) { g_cnt1[t] = 0u; g_cnt2[t] = 0u; }
    if (t == 256) g_m = 0u;
}

__global__ void k_hist(const float* __restrict__ p) {
    int i = blockIdx.x * blockDim.x + threadIdx.x;
    if (i < N) atomicAdd(&g_hist[fkey(p[i]) >> KSHIFT], 1u);
}

/* suffix scan: g_off[b] = #keys in bins strictly above b (write cursor base) */
__global__ void k_scan() {
    __shared__ unsigned cur[1024];
    const int t = threadIdx.x;
    const int base = t * 16;
    unsigned h[16]; unsigned ct = 0;
    #pragma unroll
    for (int j = 0; j < 16; j++) { h[j] = g_hist[base + j]; ct += h[j]; }
    cur[t] = ct; __syncthreads();
    for (int d = 1; d < 1024; d <<= 1) {
        unsigned v2 = cur[t] + ((t + d < 1024) ? cur[t + d] : 0u);
        __syncthreads(); cur[t] = v2; __syncthreads();
    }
    unsigned g = cur[t] - ct;
    for (int j = 15; j >= 0; j--) {
        g_off[base + j] = g;
        g += h[j];
    }
}

__global__ void k_scatter(const float* __restrict__ p) {
    int i = blockIdx.x * blockDim.x + threadIdx.x;
    if (i < N) {
        float v = p[i];
        unsigned b = fkey(v) >> KSHIFT;
        unsigned pos = atomicAdd(&g_off[b], 1u);
        g_sval[pos] = v;
        g_sidx[pos] = i;
    }
}

/* per-run insertion fix; runs = equal hi-14 key (bin tests invariant) */
__global__ void k_fix() {
    int i = blockIdx.x * blockDim.x + threadIdx.x;
    if (i >= N) return;
    unsigned bi = fkey(g_sval[i]) >> KSHIFT;
    if (i > 0 && (fkey(g_sval[i - 1]) >> KSHIFT) == bi) return;  /* not run start */
    int e = i + 1;
    while (e < N && (fkey(g_sval[e]) >> KSHIFT) == bi) e++;
    for (int a = i + 1; a < e; a++) {
        float kv = g_sval[a]; int ki = g_sidx[a];
        int j = a - 1;
        while (j >= i && g_sval[j] < kv) {
            g_sval[j + 1] = g_sval[j]; g_sidx[j + 1] = g_sidx[j]; j--;
        }
        g_sval[j + 1] = kv; g_sidx[j + 1] = ki;
    }
}

/* ===== k_count: 1024 blocks = 256 edges x 4 row-chunks, atomic accumulate == */
__global__ void k_count(int level) {
    __shared__ unsigned red[8];
    __shared__ unsigned sh;
    const int tid = threadIdx.x;            /* 256 */
    const unsigned e = (unsigned)(blockIdx.x >> 2);
    const int chunk = blockIdx.x & 3;

    unsigned edge;
    if (level == 1) {
        edge = 0x80000000u + e * 0x800000u;
    } else {
        unsigned lo1, hi1, chi1, stride2;
        derive1(&sh, tid, lo1, hi1, chi1, stride2);
        edge = lo1 + e * stride2;
    }
    const float T = unflip(edge);

    unsigned c = 0;
    #pragma unroll
    for (int g = 0; g < 2; g++) {           /* 8 rows/thread, 4-row lockstep */
        int r0 = chunk * 2048 + g * 1024 + tid;
        float v0 = __ldg(&g_sval[r0]);
        float v1 = __ldg(&g_sval[r0 + 256]);
        float v2 = __ldg(&g_sval[r0 + 512]);
        float v3 = __ldg(&g_sval[r0 + 768]);
        int lo0 = 0, hi0 = N, lo1_ = 0, hi1_ = N, lo2_ = 0, hi2_ = N, lo3_ = 0, hi3_ = N;
        #pragma unroll
        for (int st = 0; st < 14; st++) {   /* 14 guarded steps for range 8192 */
            if (lo0 < hi0)   { int m = (lo0 + hi0) >> 1;   bool pr = (v0 * __ldg(&g_sval[m]) >= T);
                               if ((v0 > 0.0f) ? pr : !pr) lo0 = m + 1; else hi0 = m; }
            if (lo1_ < hi1_) { int m = (lo1_ + hi1_) >> 1; bool pr = (v1 * __ldg(&g_sval[m]) >= T);
                               if ((v1 > 0.0f) ? pr : !pr) lo1_ = m + 1; else hi1_ = m; }
            if (lo2_ < hi2_) { int m = (lo2_ + hi2_) >> 1; bool pr = (v2 * __ldg(&g_sval[m]) >= T);
                               if ((v2 > 0.0f) ? pr : !pr) lo2_ = m + 1; else hi2_ = m; }
            if (lo3_ < hi3_) { int m = (lo3_ + hi3_) >> 1; bool pr = (v3 * __ldg(&g_sval[m]) >= T);
                               if ((v3 > 0.0f) ? pr : !pr) lo3_ = m + 1; else hi3_ = m; }
        }
        if (v0 != 0.0f) { unsigned cj = (v0 > 0.0f) ? (unsigned)lo0  : (unsigned)(N - lo0);  if (v0 * v0 >= T) cj--; c += cj; }
        if (v1 != 0.0f) { unsigned cj = (v1 > 0.0f) ? (unsigned)lo1_ : (unsigned)(N - lo1_); if (v1 * v1 >= T) cj--; c += cj; }
        if (v2 != 0.0f) { unsigned cj = (v2 > 0.0f) ? (unsigned)lo2_ : (unsigned)(N - lo2_); if (v2 * v2 >= T) cj--; c += cj; }
        if (v3 != 0.0f) { unsigned cj = (v3 > 0.0f) ? (unsigned)lo3_ : (unsigned)(N - lo3_); if (v3 * v3 >= T) cj--; c += cj; }
    }
    #pragma unroll
    for (int d = 16; d > 0; d >>= 1) c += __shfl_down_sync(0xffffffffu, c, d);
    if ((tid & 31) == 0) red[tid >> 5] = c;
    __syncthreads();
    if (tid == 0) {
        unsigned s = 0;
        #pragma unroll
        for (int i = 0; i < 8; i++) s += red[i];
        if (level == 1) atomicAdd(&g_cnt1[e], s); else atomicAdd(&g_cnt2[e], s);
    }
}

/* ===== k_enum: emit candidates with key in [lo2, hi2) (re-derives bracket) = */
__global__ void k_enum() {
    __shared__ unsigned sh;
    const int tid = threadIdx.x;
    unsigned lo1, hi1, chi1, stride2, lo2, hi2, chi2;
    derive1(&sh, tid, lo1, hi1, chi1, stride2);
    derive2(&sh, tid, lo1, hi1, chi1, stride2, lo2, hi2, chi2);

    int row = blockIdx.x * 256 + tid;
    float v = __ldg(&g_sval[row]);
    if (v == 0.0f) return;
    int bA = bsb(v, unflip(lo2));
    int bB = bsb(v, unflip(hi2));
    int m0, m1;
    if (v > 0.0f) { m0 = bB; m1 = bA; } else { m0 = bA; m1 = bB; }
    if (m1 <= m0) return;
    unsigned fb = ((unsigned)__ldg(&g_sidx[row])) << 13;
    for (int m = m0; m < m1; m++) {
        if (m == row) continue;
        unsigned pos = atomicAdd(&g_m, 1u);
        if (pos < CAP) {
            g_keys[pos]  = fkey(v * __ldg(&g_sval[m]));
            g_flats[pos] = fb + (unsigned)__ldg(&g_sidx[m]);
        }
    }
}

/* ===== k_exact: exact K-th key + tie cut among M candidates =============== */
__global__ void k_exact() {
    __shared__ unsigned hA[256];
    __shared__ unsigned hB[256];
    __shared__ unsigned s_tie[TIECAP];
    __shared__ unsigned sh;
    __shared__ unsigned s_ntie, s_binA, s_above, s_Tk, s_r, s_cut;

    const int tid = threadIdx.x;   /* 1024 */
    unsigned lo1, hi1, chi1, stride2, lo2, hi2, chi2;
    derive1(&sh, tid, lo1, hi1, chi1, stride2);
    derive2(&sh, tid, lo1, hi1, chi1, stride2, lo2, hi2, chi2);

    const unsigned M = min(g_m, CAP);
    const unsigned w = hi2 - lo2;
    const unsigned binw = (w + 255u) >> 8;

    if (tid < 256) { hA[tid] = 0u; hB[tid] = 0u; }
    if (tid == 0) s_ntie = 0u;
    __syncthreads();

    for (unsigned i = tid; i < M; i += 1024)
        atomicAdd(&hA[(__ldg(&g_keys[i]) - lo2) / binw], 1u);
    __syncthreads();

    if (tid == 0) {
        unsigned acc = chi2;
        int bA = 0;
        for (int b = 255; b >= 0; b--) {
            if (acc + hA[b] >= KTOP) { bA = b; break; }
            acc += hA[b];
        }
        s_binA = (unsigned)bA; s_above = acc;
    }
    __syncthreads();
    const unsigned binA = s_binA;
    const unsigned base = lo2 + binA * binw;

    for (unsigned i = tid; i < M; i += 1024) {
        unsigned k = __ldg(&g_keys[i]);
        if ((k - lo2) / binw == binA) atomicAdd(&hB[k - base], 1u);
    }
    __syncthreads();

    if (tid == 0) {
        unsigned acc = s_above;
        unsigned off = 0;
        for (int o = (int)binw - 1; o >= 0; o--) {
            if (acc + hB[o] >= KTOP) { off = (unsigned)o; break; }
            acc += hB[o];
        }
        s_Tk = base + off;
        s_r = KTOP - acc;
    }
    __syncthreads();
    const unsigned Tk = s_Tk, r = s_r;

    for (unsigned i = tid; i < M; i += 1024) {
        if (__ldg(&g_keys[i]) == Tk) {
            unsigned pos = atomicAdd(&s_ntie, 1u);
            if (pos < TIECAP) s_tie[pos] = __ldg(&g_flats[i]);
        }
    }
    __syncthreads();

    unsigned nt = min(s_ntie, (unsigned)TIECAP);
    if (tid == 0) s_cut = (r >= nt) ? 0xFFFFFFFFu : 0u;
    __syncthreads();
    if (r < nt) {
        for (unsigned i = tid; i < nt; i += 1024) {
            unsigned x = s_tie[i];
            unsigned rk = 0;
            for (unsigned j = 0; j < nt; j++) rk += (s_tie[j] < x) ? 1u : 0u;
            if (rk == r) s_cut = x;
        }
    }
    __syncthreads();
    if (tid == 0) { g_thr = unflip(Tk); g_cut = s_cut; }
}

/* ================= fused output pass (validated, roofline) ================ */
__device__ __forceinline__ float edgev(float v, float thr, unsigned flat, unsigned cut, bool diag) {
    bool ok = ((v > thr) | ((v == thr) & (flat < cut))) & (!diag);
    return ok ? 1.0f : 0.0f;
}

__global__ void k_out(const float* __restrict__ p, float4* __restrict__ out) {
    int row = blockIdx.y;
    float pi = __ldg(p + row);
    float thr = g_thr;
    unsigned cut = g_cut;
    const float4* __restrict__ q4 = (const float4*)p;
    int f0 = blockIdx.x * 1024 + threadIdx.x;
    unsigned fbase = ((unsigned)row) << 13;
    unsigned outrow = ((unsigned)row) << 11;
    #pragma unroll
    for (int k = 0; k < 4; k++) {
        int f = f0 + k * 256;
        float4 q = __ldg(q4 + f);
        unsigned j0 = ((unsigned)f) << 2;
        float4 o;
        o.x = edgev(pi * q.x, thr, fbase + j0 + 0u, cut, (j0 + 0u) == (unsigned)row);
        o.y = edgev(pi * q.y, thr, fbase + j0 + 1u, cut, (j0 + 1u) == (unsigned)row);
        o.z = edgev(pi * q.z, thr, fbase + j0 + 2u, cut, (j0 + 2u) == (unsigned)row);
        o.w = edgev(pi * q.w, thr, fbase + j0 + 3u, cut, (j0 + 3u) == (unsigned)row);
        __stcs(out + outrow + (unsigned)f, o);
    }
}

extern "C" void kernel_launch(void* const* d_in, const int* in_sizes, int n_in,
                              void* d_out, int out_size) {
    const float* p = (const float*)d_in[0];
    float* out = (float*)d_out;
    (void)in_sizes; (void)n_in; (void)out_size;

    k_zero<<<64, 256>>>();
    k_hist<<<32, 256>>>(p);
    k_scan<<<1, 1024>>>();
    k_scatter<<<32, 256>>>(p);
    k_fix<<<32, 256>>>();
    k_count<<<1024, 256>>>(1);
    k_count<<<1024, 256>>>(2);
    k_enum<<<32, 256>>>();
    k_exact<<<1, 1024>>>();

    dim3 grid(2, N);
    k_out<<<grid, 256>>>(p, (float4*)out);
}